// round 14
// baseline (speedup 1.0000x reference)
#include <cuda_runtime.h>
#include <math.h>

#define S 2048
#define NBLK 148
#define NTHR 512
#define MAX_ROWS 14   // ceil(S / NBLK)

// Normalized k: [b][n][blade] = 128 KB (L2-resident)
__device__ __align__(256) float g_k[2][S][8];
// Grid-barrier state (epoch is monotonic -> safe across graph replays)
__device__ unsigned int g_count = 0;
__device__ unsigned int g_epoch = 0;

// 256-bit streaming store (output never re-read).
__device__ __forceinline__ void stg256_cs(float* p, const float4& a, const float4& b)
{
    asm volatile("st.global.cs.v8.f32 [%0], {%1,%2,%3,%4,%5,%6,%7,%8};"
                 :: "l"(p),
                    "f"(a.x), "f"(a.y), "f"(a.z), "f"(a.w),
                    "f"(b.x), "f"(b.y), "f"(b.z), "f"(b.w)
                 : "memory");
}

// 256-bit non-coherent load: ONLY for immutable inputs (x, Wq, Wk).
__device__ __forceinline__ void ldg256(const float* p, float4& a, float4& b)
{
    asm volatile("ld.global.nc.v8.f32 {%0,%1,%2,%3,%4,%5,%6,%7}, [%8];"
                 : "=f"(a.x), "=f"(a.y), "=f"(a.z), "=f"(a.w),
                   "=f"(b.x), "=f"(b.y), "=f"(b.z), "=f"(b.w)
                 : "l"(p));
}

// Coherent L2 load for g_k (written earlier in the SAME launch).
__device__ __forceinline__ float4 ldg128_cg(const float* p)
{
    float4 a;
    asm volatile("ld.global.cg.v4.f32 {%0,%1,%2,%3}, [%4];"
                 : "=f"(a.x), "=f"(a.y), "=f"(a.z), "=f"(a.w) : "l"(p));
    return a;
}

// 16 accumulators: acc[0..7] = b0 blades, acc[8..15] = b1 blades
__device__ __forceinline__ void mv_fma16(float* acc, const float4 (&xr)[4][4],
                                         const float4* wv)
{
#pragma unroll
    for (int j = 0; j < 4; j++) {
        const float4 x0a = xr[j][0], x0b = xr[j][1];
        const float4 x1a = xr[j][2], x1b = xr[j][3];
        const float4 ww = wv[j];
        acc[0]  = fmaf(ww.x, x0a.x, acc[0]);
        acc[1]  = fmaf(ww.y, x0a.y, acc[1]);
        acc[2]  = fmaf(ww.y, x0a.z, acc[2]);
        acc[3]  = fmaf(ww.y, x0a.w, acc[3]);
        acc[4]  = fmaf(ww.z, x0b.x, acc[4]);
        acc[5]  = fmaf(ww.z, x0b.y, acc[5]);
        acc[6]  = fmaf(ww.z, x0b.z, acc[6]);
        acc[7]  = fmaf(ww.w, x0b.w, acc[7]);
        acc[8]  = fmaf(ww.x, x1a.x, acc[8]);
        acc[9]  = fmaf(ww.y, x1a.y, acc[9]);
        acc[10] = fmaf(ww.y, x1a.z, acc[10]);
        acc[11] = fmaf(ww.y, x1a.w, acc[11]);
        acc[12] = fmaf(ww.z, x1b.x, acc[12]);
        acc[13] = fmaf(ww.z, x1b.y, acc[13]);
        acc[14] = fmaf(ww.z, x1b.z, acc[14]);
        acc[15] = fmaf(ww.w, x1b.w, acc[15]);
    }
}

// 16-value butterfly + half-merge: every lane ends with the full warp sum
// of value (lane & 15) in acc[0].
__device__ __forceinline__ void bfly16(float* acc, int lane)
{
#pragma unroll
    for (int d = 8; d >= 1; d >>= 1) {
#pragma unroll
        for (int i = 0; i < d; i++) {
            const bool hi = (lane & d) != 0;
            const float keep = hi ? acc[i + d] : acc[i];
            const float send = hi ? acc[i] : acc[i + d];
            acc[i] = keep + __shfl_xor_sync(0xffffffffu, send, d);
        }
    }
    acc[0] += __shfl_xor_sync(0xffffffffu, acc[0], 16);
}

// Normalization denominator for blade index i of an 8-vector e[] with row n.
__device__ __forceinline__ float norm_den(const float* e, int i, int n,
                                          const float* a)
{
    const int g = (i == 0) ? 0 : (i < 4) ? 1 : (i < 7) ? 2 : 3;
    float nr;
    if      (g == 0) nr = fabsf(e[0]);
    else if (g == 1) nr = sqrtf(e[1] * e[1] + e[2] * e[2] + e[3] * e[3]);
    else if (g == 2) nr = sqrtf(e[4] * e[4] + e[5] * e[5] + e[6] * e[6]);
    else             nr = fabsf(e[7]);
    const float sa = 1.f / (1.f + expf(-a[n * 4 + g]));
    return sa * (nr - 1.f) + 1.f + 1e-6f;
}

// Cl(3,0) geometric product: o = q * k (hardcoded Cayley signs).
__device__ __forceinline__ void gp8(float4& o_lo, float4& o_hi, const float* q,
                                    const float4& ka, const float4& kb)
{
    const float k0 = ka.x, k1 = ka.y, k2 = ka.z, k3 = ka.w;
    const float k4 = kb.x, k5 = kb.y, k6 = kb.z, k7 = kb.w;
    o_lo.x = q[0]*k0 + q[1]*k1 + q[2]*k2 + q[3]*k3 - q[4]*k4 - q[5]*k5 - q[6]*k6 - q[7]*k7;
    o_lo.y = q[0]*k1 + q[1]*k0 - q[2]*k4 + q[4]*k2 - q[3]*k5 + q[5]*k3 - q[6]*k7 - q[7]*k6;
    o_lo.z = q[0]*k2 + q[2]*k0 + q[1]*k4 - q[4]*k1 - q[3]*k6 + q[6]*k3 + q[5]*k7 + q[7]*k5;
    o_lo.w = q[0]*k3 + q[3]*k0 + q[1]*k5 - q[5]*k1 + q[2]*k6 - q[6]*k2 - q[4]*k7 - q[7]*k4;
    o_hi.x = q[0]*k4 + q[4]*k0 + q[1]*k2 - q[2]*k1 + q[3]*k7 + q[7]*k3 - q[5]*k6 + q[6]*k5;
    o_hi.y = q[0]*k5 + q[5]*k0 + q[1]*k3 - q[3]*k1 - q[2]*k7 - q[7]*k2 + q[4]*k6 - q[6]*k4;
    o_hi.z = q[0]*k6 + q[6]*k0 + q[2]*k3 - q[3]*k2 + q[1]*k7 + q[7]*k1 - q[4]*k5 + q[5]*k4;
    o_hi.w = q[0]*k7 + q[7]*k0 + q[1]*k6 + q[6]*k1 - q[2]*k5 - q[5]*k2 + q[3]*k4 + q[4]*k3;
}

// ---------------------------------------------------------------------------
// Single fused persistent kernel.
// Phase 1: k = normalize(mv_linear(x, Wk)) (barrier-free rows + fixup).
// Grid barrier (all 148 blocks resident; epoch counter, replay-safe).
// Phase 2: per row n: q[.][n] (Wq read + 2 block barriers) then the full
//          output row out[.][n][.][.] (128 KB streaming stores) -> Wq reads
//          interleave with the write stream.
// ---------------------------------------------------------------------------
__global__ __launch_bounds__(NTHR) void fused_kernel(
    const float* __restrict__ x,    // (2, S, 8)
    const float* __restrict__ Wq,   // (S, S, 4)
    const float* __restrict__ Wk,   // (S, S, 4)
    const float* __restrict__ a,    // (3000, 4)
    float* __restrict__ out)        // (2, S, S, 8)
{
    const int tid  = threadIdx.x;
    const int warp = tid >> 5, lane = tid & 31;
    const int m0   = tid * 4;
    const size_t coff = (size_t)m0 * 4;

    __shared__ float part[MAX_ROWS][16][16];
    __shared__ float qpart[16][16];
    __shared__ float qsh[16];

    // x slice register-resident for the whole kernel.
    float4 xr[4][4];
#pragma unroll
    for (int j = 0; j < 4; j++) {
        ldg256(x + (size_t)(m0 + j) * 8,     xr[j][0], xr[j][1]);
        ldg256(x + (size_t)(S + m0 + j) * 8, xr[j][2], xr[j][3]);
    }

    // ================= Phase 1: k =================
    float4 wreg[4];
    {
        const float* p = Wk + (size_t)blockIdx.x * S * 4 + coff;
        ldg256(p,     wreg[0], wreg[1]);
        ldg256(p + 8, wreg[2], wreg[3]);
    }

    int r = 0;
    for (int n = blockIdx.x; n < S; n += NBLK, r++) {
        float v[16];
#pragma unroll
        for (int i = 0; i < 16; i++) v[i] = 0.f;
        mv_fma16(v, xr, wreg);
        const int nn = n + NBLK;
        if (nn < S) {
            const float* p = Wk + (size_t)nn * S * 4 + coff;
            ldg256(p,     wreg[0], wreg[1]);
            ldg256(p + 8, wreg[2], wreg[3]);
        }
        bfly16(v, lane);
        if (lane < 16) part[r][warp][lane] = v[0];
    }
    __syncthreads();
    const int nrows = r;
    if (warp < nrows) {
        const int n = blockIdx.x + warp * NBLK;
        float s = 0.f;
#pragma unroll
        for (int p = 0; p < 16; p++) s += part[warp][p][lane];
        // Gather the 8 blade values of this lane's b-group via shuffles.
        float e[8];
        const int base = lane & ~7;
#pragma unroll
        for (int i = 0; i < 8; i++)
            e[i] = __shfl_sync(0xffffffffu, s, base + i);
        if (lane < 16) {
            const int i = lane & 7, b = lane >> 3;
            g_k[b][n][i] = s / norm_den(e, i, n, a);
        }
    }

    // Prefetch first Wq row NOW — latency hides under the barrier spin.
    {
        const float* p = Wq + (size_t)blockIdx.x * S * 4 + coff;
        ldg256(p,     wreg[0], wreg[1]);
        ldg256(p + 8, wreg[2], wreg[3]);
    }

    // ================= Grid barrier =================
    __threadfence();
    __syncthreads();
    if (tid == 0) {
        const unsigned e0 = atomicAdd(&g_epoch, 0u);
        const unsigned arr = atomicAdd(&g_count, 1u);
        if (arr == NBLK - 1) {
            atomicExch(&g_count, 0u);
            __threadfence();
            atomicAdd(&g_epoch, 1u);
        } else {
            while (atomicAdd(&g_epoch, 0u) == e0) {}
        }
    }
    __syncthreads();

    // ================= Phase 2: q + output row =================
    for (int n = blockIdx.x; n < S; n += NBLK) {
        float v[16];
#pragma unroll
        for (int i = 0; i < 16; i++) v[i] = 0.f;
        mv_fma16(v, xr, wreg);
        const int nn = n + NBLK;
        if (nn < S) {
            const float* p = Wq + (size_t)nn * S * 4 + coff;
            ldg256(p,     wreg[0], wreg[1]);
            ldg256(p + 8, wreg[2], wreg[3]);
        }
        bfly16(v, lane);
        if (lane < 16) qpart[warp][lane] = v[0];
        __syncthreads();
        if (warp == 0) {
            float s = 0.f;
#pragma unroll
            for (int p = 0; p < 16; p++) s += qpart[p][lane];
            float e[8];
            const int base = lane & ~7;
#pragma unroll
            for (int i = 0; i < 8; i++)
                e[i] = __shfl_sync(0xffffffffu, s, base + i);
            if (lane < 16) {
                const int i = lane & 7;
                qsh[lane] = s / norm_den(e, i, n, a);
            }
        }
        __syncthreads();

        float q0[8], q1[8];
#pragma unroll
        for (int i = 0; i < 8; i++) { q0[i] = qsh[i]; q1[i] = qsh[8 + i]; }

        float* o0 = out + (size_t)n * S * 8;            // b = 0
        float* o1 = out + (size_t)(S + n) * S * 8;      // b = 1

#pragma unroll
        for (int j = 0; j < 4; j++) {
            const int t = tid + j * NTHR;
            {
                const float4 ka = ldg128_cg(&g_k[0][t][0]);
                const float4 kb = ldg128_cg(&g_k[0][t][4]);
                float4 o_lo, o_hi;
                gp8(o_lo, o_hi, q0, ka, kb);
                stg256_cs(o0 + (size_t)t * 8, o_lo, o_hi);
            }
            {
                const float4 ka = ldg128_cg(&g_k[1][t][0]);
                const float4 kb = ldg128_cg(&g_k[1][t][4]);
                float4 o_lo, o_hi;
                gp8(o_lo, o_hi, q1, ka, kb);
                stg256_cs(o1 + (size_t)t * 8, o_lo, o_hi);
            }
        }
        // qsh/qpart reuse is ordered by the next iteration's barriers.
    }
}

extern "C" void kernel_launch(void* const* d_in, const int* in_sizes, int n_in,
                              void* d_out, int out_size)
{
    const float* x  = (const float*)d_in[0];   // (2, 2048, 8)
    const float* Wq = (const float*)d_in[1];   // (2048, 2048, 4)
    const float* Wk = (const float*)d_in[2];   // (2048, 2048, 4)
    const float* a  = (const float*)d_in[3];   // (3000, 4)
    float* out = (float*)d_out;                // (2, 2048, 2048, 8)

    fused_kernel<<<NBLK, NTHR>>>(x, Wq, Wk, a, out);
}

// round 16
// speedup vs baseline: 1.1770x; 1.1770x over previous
#include <cuda_runtime.h>
#include <math.h>

#define S 2048
#define NBLK 148
#define NTHR 512
#define MAX_ROWS 14   // ceil(S / NBLK)

// Normalized k: [b][n][blade] = 128 KB (L2-resident)
__device__ __align__(256) float g_k[2][S][8];

// 256-bit streaming store (output never re-read).
__device__ __forceinline__ void stg256_cs(float* p, const float4& a, const float4& b)
{
    asm volatile("st.global.cs.v8.f32 [%0], {%1,%2,%3,%4,%5,%6,%7,%8};"
                 :: "l"(p),
                    "f"(a.x), "f"(a.y), "f"(a.z), "f"(a.w),
                    "f"(b.x), "f"(b.y), "f"(b.z), "f"(b.w)
                 : "memory");
}

// 256-bit non-coherent load (immutable within the consuming launch).
__device__ __forceinline__ void ldg256(const float* p, float4& a, float4& b)
{
    asm volatile("ld.global.nc.v8.f32 {%0,%1,%2,%3,%4,%5,%6,%7}, [%8];"
                 : "=f"(a.x), "=f"(a.y), "=f"(a.z), "=f"(a.w),
                   "=f"(b.x), "=f"(b.y), "=f"(b.z), "=f"(b.w)
                 : "l"(p));
}

// 16 accumulators: acc[0..7] = b0 blades, acc[8..15] = b1 blades
__device__ __forceinline__ void mv_fma16(float* acc,
                                         const float4& x0a, const float4& x0b,
                                         const float4& x1a, const float4& x1b,
                                         const float4& ww)
{
    acc[0]  = fmaf(ww.x, x0a.x, acc[0]);
    acc[1]  = fmaf(ww.y, x0a.y, acc[1]);
    acc[2]  = fmaf(ww.y, x0a.z, acc[2]);
    acc[3]  = fmaf(ww.y, x0a.w, acc[3]);
    acc[4]  = fmaf(ww.z, x0b.x, acc[4]);
    acc[5]  = fmaf(ww.z, x0b.y, acc[5]);
    acc[6]  = fmaf(ww.z, x0b.z, acc[6]);
    acc[7]  = fmaf(ww.w, x0b.w, acc[7]);
    acc[8]  = fmaf(ww.x, x1a.x, acc[8]);
    acc[9]  = fmaf(ww.y, x1a.y, acc[9]);
    acc[10] = fmaf(ww.y, x1a.z, acc[10]);
    acc[11] = fmaf(ww.y, x1a.w, acc[11]);
    acc[12] = fmaf(ww.z, x1b.x, acc[12]);
    acc[13] = fmaf(ww.z, x1b.y, acc[13]);
    acc[14] = fmaf(ww.z, x1b.z, acc[14]);
    acc[15] = fmaf(ww.w, x1b.w, acc[15]);
}

// 16-value butterfly + half-merge: every lane ends with the full warp sum
// of value (lane & 15) in acc[0].
__device__ __forceinline__ void bfly16(float* acc, int lane)
{
#pragma unroll
    for (int d = 8; d >= 1; d >>= 1) {
#pragma unroll
        for (int i = 0; i < d; i++) {
            const bool hi = (lane & d) != 0;
            const float keep = hi ? acc[i + d] : acc[i];
            const float send = hi ? acc[i] : acc[i + d];
            acc[i] = keep + __shfl_xor_sync(0xffffffffu, send, d);
        }
    }
    acc[0] += __shfl_xor_sync(0xffffffffu, acc[0], 16);
}

// Normalization denominator for blade i of 8-vector e[], row n.
__device__ __forceinline__ float norm_den(const float* e, int i, int n,
                                          const float* a)
{
    const int g = (i == 0) ? 0 : (i < 4) ? 1 : (i < 7) ? 2 : 3;
    float nr;
    if      (g == 0) nr = fabsf(e[0]);
    else if (g == 1) nr = sqrtf(e[1] * e[1] + e[2] * e[2] + e[3] * e[3]);
    else if (g == 2) nr = sqrtf(e[4] * e[4] + e[5] * e[5] + e[6] * e[6]);
    else             nr = fabsf(e[7]);
    const float sa = 1.f / (1.f + expf(-a[n * 4 + g]));
    return sa * (nr - 1.f) + 1.f + 1e-6f;
}

// Cl(3,0) geometric product o = q * k (hardcoded Cayley signs).
__device__ __forceinline__ void gp8(float4& o_lo, float4& o_hi, const float* q,
                                    const float4& ka, const float4& kb)
{
    const float k0 = ka.x, k1 = ka.y, k2 = ka.z, k3 = ka.w;
    const float k4 = kb.x, k5 = kb.y, k6 = kb.z, k7 = kb.w;
    o_lo.x = q[0]*k0 + q[1]*k1 + q[2]*k2 + q[3]*k3 - q[4]*k4 - q[5]*k5 - q[6]*k6 - q[7]*k7;
    o_lo.y = q[0]*k1 + q[1]*k0 - q[2]*k4 + q[4]*k2 - q[3]*k5 + q[5]*k3 - q[6]*k7 - q[7]*k6;
    o_lo.z = q[0]*k2 + q[2]*k0 + q[1]*k4 - q[4]*k1 - q[3]*k6 + q[6]*k3 + q[5]*k7 + q[7]*k5;
    o_lo.w = q[0]*k3 + q[3]*k0 + q[1]*k5 - q[5]*k1 + q[2]*k6 - q[6]*k2 - q[4]*k7 - q[7]*k4;
    o_hi.x = q[0]*k4 + q[4]*k0 + q[1]*k2 - q[2]*k1 + q[3]*k7 + q[7]*k3 - q[5]*k6 + q[6]*k5;
    o_hi.y = q[0]*k5 + q[5]*k0 + q[1]*k3 - q[3]*k1 - q[2]*k7 - q[7]*k2 + q[4]*k6 - q[6]*k4;
    o_hi.z = q[0]*k6 + q[6]*k0 + q[2]*k3 - q[3]*k2 + q[1]*k7 + q[7]*k1 - q[4]*k5 + q[5]*k4;
    o_hi.w = q[0]*k7 + q[7]*k0 + q[1]*k6 + q[6]*k1 - q[2]*k5 - q[5]*k2 + q[3]*k4 + q[4]*k3;
}

// ---------------------------------------------------------------------------
// Kernel A: k = normalize(mv_linear(x, Wk)). Persistent 148x512, barrier-free
// rows, register-resident x, cross-row Wk prefetch, fused fixup tail.
// ---------------------------------------------------------------------------
__global__ __launch_bounds__(NTHR) void k_kernel(
    const float* __restrict__ x,    // (2, S, 8)
    const float* __restrict__ Wk,   // (S, S, 4)
    const float* __restrict__ a)    // (3000, 4)
{
    const int tid  = threadIdx.x;
    const int warp = tid >> 5, lane = tid & 31;
    const int m0   = tid * 4;
    const size_t coff = (size_t)m0 * 4;

    __shared__ float part[MAX_ROWS][16][16];

    float4 xr[4][4];
#pragma unroll
    for (int j = 0; j < 4; j++) {
        ldg256(x + (size_t)(m0 + j) * 8,     xr[j][0], xr[j][1]);
        ldg256(x + (size_t)(S + m0 + j) * 8, xr[j][2], xr[j][3]);
    }

    float4 wreg[4];
    {
        const float* p = Wk + (size_t)blockIdx.x * S * 4 + coff;
        ldg256(p,     wreg[0], wreg[1]);
        ldg256(p + 8, wreg[2], wreg[3]);
    }

    int r = 0;
    for (int n = blockIdx.x; n < S; n += NBLK, r++) {
        float v[16];
#pragma unroll
        for (int i = 0; i < 16; i++) v[i] = 0.f;
#pragma unroll
        for (int j = 0; j < 4; j++)
            mv_fma16(v, xr[j][0], xr[j][1], xr[j][2], xr[j][3], wreg[j]);
        const int nn = n + NBLK;
        if (nn < S) {
            const float* p = Wk + (size_t)nn * S * 4 + coff;
            ldg256(p,     wreg[0], wreg[1]);
            ldg256(p + 8, wreg[2], wreg[3]);
        }
        bfly16(v, lane);
        if (lane < 16) part[r][warp][lane] = v[0];
    }
    __syncthreads();
    if (warp < r) {
        const int n = blockIdx.x + warp * NBLK;
        // lane & 15: lanes 16-31 duplicate 0-15 (bounds-safe; they never write)
        float s = 0.f;
#pragma unroll
        for (int p = 0; p < 16; p++) s += part[warp][p][lane & 15];
        float e[8];
        const int base = lane & 8;   // 8-value group within the 16 valid values
#pragma unroll
        for (int i = 0; i < 8; i++)
            e[i] = __shfl_sync(0xffffffffu, s, base + i);
        if (lane < 16) {
            const int i = lane & 7, b = lane >> 3;
            g_k[b][n][i] = s / norm_den(e, i, n, a);
        }
    }
}

// ---------------------------------------------------------------------------
// Kernel B: one block per output row n. Compute q[.][n] (Wq row m-strided,
// x from L1/L2), reduce+normalize once, then stream the full 128 KB output
// row: Wq reads interleave with the store stream across ~600 resident blocks.
// ---------------------------------------------------------------------------
__global__ __launch_bounds__(256) void qrow_kernel(
    const float* __restrict__ x,    // (2, S, 8)
    const float* __restrict__ Wq,   // (S, S, 4)
    const float* __restrict__ a,    // (3000, 4)
    float* __restrict__ out)        // (2, S, S, 8)
{
    const int n   = blockIdx.x;
    const int tid = threadIdx.x;
    const int warp = tid >> 5, lane = tid & 31;

    __shared__ float qpart[8][16];
    __shared__ float qsh[16];

    const float4* WqR = reinterpret_cast<const float4*>(Wq + (size_t)n * S * 4);

    // ---- q compute: m-strided over the Wq row ----
    float v[16];
#pragma unroll
    for (int i = 0; i < 16; i++) v[i] = 0.f;
#pragma unroll
    for (int it = 0; it < 8; it++) {
        const int m = tid + it * 256;
        const float4 w = __ldcs(&WqR[m]);
        float4 x0a, x0b, x1a, x1b;
        ldg256(x + (size_t)m * 8,       x0a, x0b);
        ldg256(x + (size_t)(S + m) * 8, x1a, x1b);
        mv_fma16(v, x0a, x0b, x1a, x1b, w);
    }
    bfly16(v, lane);
    if (lane < 16) qpart[warp][lane] = v[0];
    __syncthreads();

    if (warp == 0) {
        // lane & 15: bounds-safe for lanes 16-31 (results unused there)
        float s = 0.f;
#pragma unroll
        for (int p = 0; p < 8; p++) s += qpart[p][lane & 15];
        float e[8];
        const int base = lane & 8;
#pragma unroll
        for (int i = 0; i < 8; i++)
            e[i] = __shfl_sync(0xffffffffu, s, base + i);
        if (lane < 16) {
            const int i = lane & 7;
            qsh[lane] = s / norm_den(e, i, n, a);
        }
    }
    __syncthreads();

    float q0[8], q1[8];
#pragma unroll
    for (int i = 0; i < 8; i++) { q0[i] = qsh[i]; q1[i] = qsh[8 + i]; }

    float* o0 = out + (size_t)n * S * 8;        // b = 0
    float* o1 = out + (size_t)(S + n) * S * 8;  // b = 1
    const float* K = &g_k[0][0][0];

    // ---- stream the full output row (2 batches x 2048 t) ----
#pragma unroll
    for (int j = 0; j < 8; j++) {
        const int t = tid + j * 256;
        {
            float4 ka, kb;
            ldg256(K + (size_t)t * 8, ka, kb);            // g_k[0][t]
            float4 o_lo, o_hi;
            gp8(o_lo, o_hi, q0, ka, kb);
            stg256_cs(o0 + (size_t)t * 8, o_lo, o_hi);
        }
        {
            float4 ka, kb;
            ldg256(K + (size_t)(S + t) * 8, ka, kb);      // g_k[1][t]
            float4 o_lo, o_hi;
            gp8(o_lo, o_hi, q1, ka, kb);
            stg256_cs(o1 + (size_t)t * 8, o_lo, o_hi);
        }
    }
}

extern "C" void kernel_launch(void* const* d_in, const int* in_sizes, int n_in,
                              void* d_out, int out_size)
{
    const float* x  = (const float*)d_in[0];   // (2, 2048, 8)
    const float* Wq = (const float*)d_in[1];   // (2048, 2048, 4)
    const float* Wk = (const float*)d_in[2];   // (2048, 2048, 4)
    const float* a  = (const float*)d_in[3];   // (3000, 4)
    float* out = (float*)d_out;                // (2, 2048, 2048, 8)

    k_kernel<<<NBLK, NTHR>>>(x, Wk, a);
    qrow_kernel<<<S, 256>>>(x, Wq, a, out);
}

// round 17
// speedup vs baseline: 1.3030x; 1.1070x over previous
#include <cuda_runtime.h>
#include <math.h>

#define S 2048
#define B 2
#define STILE 2
#define QK_THREADS 512
#define QK_BLOCKS 148
#define MAX_ROWS 14   // ceil(S / QK_BLOCKS)

// Normalized q and k: [which(q=0,k=1)][b][n][blade] = 256 KB
__device__ __align__(256) float g_qk[2][B][S][8];

// 256-bit global store, streaming (evict-first): output is never re-read.
__device__ __forceinline__ void stg256_cs(float* p, const float4& a, const float4& b)
{
    asm volatile("st.global.cs.v8.f32 [%0], {%1,%2,%3,%4,%5,%6,%7,%8};"
                 :: "l"(p),
                    "f"(a.x), "f"(a.y), "f"(a.z), "f"(a.w),
                    "f"(b.x), "f"(b.y), "f"(b.z), "f"(b.w)
                 : "memory");
}

__device__ __forceinline__ void ldg256(const float* p, float4& a, float4& b)
{
    asm volatile("ld.global.nc.v8.f32 {%0,%1,%2,%3,%4,%5,%6,%7}, [%8];"
                 : "=f"(a.x), "=f"(a.y), "=f"(a.z), "=f"(a.w),
                   "=f"(b.x), "=f"(b.y), "=f"(b.z), "=f"(b.w)
                 : "l"(p));
}

// ---------------------------------------------------------------------------
// Kernel 1 (persistent, barrier-free hot loop, fused fixup tail):
// 148 blocks x 512 threads; thread t owns m in [4t, 4t+4); x register-
// resident; cross-row W prefetch. Per-warp partials staged in SMEM; after
// the row loop, ONE __syncthreads and each warp normalizes one row.
// ---------------------------------------------------------------------------
__global__ __launch_bounds__(QK_THREADS) void qk_main(
    const float* __restrict__ x,    // (B, S, 8)
    const float* __restrict__ Wq,   // (S, S, 4)
    const float* __restrict__ Wk,   // (S, S, 4)
    const float* __restrict__ a)    // (3000, 4)
{
    const int tid  = threadIdx.x;
    const int warp = tid >> 5, lane = tid & 31;
    const int m0   = tid * 4;

    __shared__ float part[MAX_ROWS][16][32];

    // x slice: xr[j][0..1] = x[b0][m0+j], xr[j][2..3] = x[b1][m0+j]
    float4 xr[4][4];
#pragma unroll
    for (int j = 0; j < 4; j++) {
        ldg256(x + (size_t)(m0 + j) * 8,     xr[j][0], xr[j][1]);
        ldg256(x + (size_t)(S + m0 + j) * 8, xr[j][2], xr[j][3]);
    }

    const size_t coff = (size_t)m0 * 4;

    // Preload first row's W
    float4 wq[4], wk[4];
    {
        const float* WqR = Wq + (size_t)blockIdx.x * S * 4 + coff;
        const float* WkR = Wk + (size_t)blockIdx.x * S * 4 + coff;
        ldg256(WqR,     wq[0], wq[1]);
        ldg256(WqR + 8, wq[2], wq[3]);
        ldg256(WkR,     wk[0], wk[1]);
        ldg256(WkR + 8, wk[2], wk[3]);
    }

    int r = 0;
    for (int n = blockIdx.x; n < S; n += QK_BLOCKS, r++) {
        const int nn = n + QK_BLOCKS;

        // ---- q phase: v[0..7]=b0 blades, v[8..15]=b1 blades ----
        float v[16];
#pragma unroll
        for (int i = 0; i < 16; i++) v[i] = 0.f;
#pragma unroll
        for (int j = 0; j < 4; j++) {
            const float4 x0a = xr[j][0], x0b = xr[j][1];
            const float4 x1a = xr[j][2], x1b = xr[j][3];
            const float4 w = wq[j];
            v[0]  = fmaf(w.x, x0a.x, v[0]);
            v[1]  = fmaf(w.y, x0a.y, v[1]);
            v[2]  = fmaf(w.y, x0a.z, v[2]);
            v[3]  = fmaf(w.y, x0a.w, v[3]);
            v[4]  = fmaf(w.z, x0b.x, v[4]);
            v[5]  = fmaf(w.z, x0b.y, v[5]);
            v[6]  = fmaf(w.z, x0b.z, v[6]);
            v[7]  = fmaf(w.w, x0b.w, v[7]);
            v[8]  = fmaf(w.x, x1a.x, v[8]);
            v[9]  = fmaf(w.y, x1a.y, v[9]);
            v[10] = fmaf(w.y, x1a.z, v[10]);
            v[11] = fmaf(w.y, x1a.w, v[11]);
            v[12] = fmaf(w.z, x1b.x, v[12]);
            v[13] = fmaf(w.z, x1b.y, v[13]);
            v[14] = fmaf(w.z, x1b.z, v[14]);
            v[15] = fmaf(w.w, x1b.w, v[15]);
        }

        // PREFETCH next row's Wq (wq regs dead after q-FMAs)
        if (nn < S) {
            const float* WqR = Wq + (size_t)nn * S * 4 + coff;
            ldg256(WqR,     wq[0], wq[1]);
            ldg256(WqR + 8, wq[2], wq[3]);
        }

        // Multi-value butterfly: lane L ends with full warp sum of acc L&15.
#pragma unroll
        for (int d = 8; d >= 1; d >>= 1) {
#pragma unroll
            for (int i = 0; i < d; i++) {
                const bool hi = (lane & d) != 0;
                const float keep = hi ? v[i + d] : v[i];
                const float send = hi ? v[i] : v[i + d];
                v[i] = keep + __shfl_xor_sync(0xffffffffu, send, d);
            }
        }
        v[0] += __shfl_xor_sync(0xffffffffu, v[0], 16);
        if (lane < 16) part[r][warp][lane] = v[0];

        // ---- k phase ----
#pragma unroll
        for (int i = 0; i < 16; i++) v[i] = 0.f;
#pragma unroll
        for (int j = 0; j < 4; j++) {
            const float4 x0a = xr[j][0], x0b = xr[j][1];
            const float4 x1a = xr[j][2], x1b = xr[j][3];
            const float4 w = wk[j];
            v[0]  = fmaf(w.x, x0a.x, v[0]);
            v[1]  = fmaf(w.y, x0a.y, v[1]);
            v[2]  = fmaf(w.y, x0a.z, v[2]);
            v[3]  = fmaf(w.y, x0a.w, v[3]);
            v[4]  = fmaf(w.z, x0b.x, v[4]);
            v[5]  = fmaf(w.z, x0b.y, v[5]);
            v[6]  = fmaf(w.z, x0b.z, v[6]);
            v[7]  = fmaf(w.w, x0b.w, v[7]);
            v[8]  = fmaf(w.x, x1a.x, v[8]);
            v[9]  = fmaf(w.y, x1a.y, v[9]);
            v[10] = fmaf(w.y, x1a.z, v[10]);
            v[11] = fmaf(w.y, x1a.w, v[11]);
            v[12] = fmaf(w.z, x1b.x, v[12]);
            v[13] = fmaf(w.z, x1b.y, v[13]);
            v[14] = fmaf(w.z, x1b.z, v[14]);
            v[15] = fmaf(w.w, x1b.w, v[15]);
        }

        // PREFETCH next row's Wk (wk regs dead after k-FMAs)
        if (nn < S) {
            const float* WkR = Wk + (size_t)nn * S * 4 + coff;
            ldg256(WkR,     wk[0], wk[1]);
            ldg256(WkR + 8, wk[2], wk[3]);
        }

#pragma unroll
        for (int d = 8; d >= 1; d >>= 1) {
#pragma unroll
            for (int i = 0; i < d; i++) {
                const bool hi = (lane & d) != 0;
                const float keep = hi ? v[i + d] : v[i];
                const float send = hi ? v[i] : v[i + d];
                v[i] = keep + __shfl_xor_sync(0xffffffffu, send, d);
            }
        }
        v[0] += __shfl_xor_sync(0xffffffffu, v[0], 16);
        if (lane < 16) part[r][warp][16 + lane] = v[0];
    }

    // ---- Fused fixup: one barrier, then warp w normalizes local row w ----
    __syncthreads();
    const int nrows = r;
    if (warp < nrows) {
        const int n = blockIdx.x + warp * QK_BLOCKS;

        float s = 0.f;
#pragma unroll
        for (int p = 0; p < 16; p++) s += part[warp][p][lane];

        // Gather the 8 blade values of this lane's (which,b) group.
        const int base = lane & ~7;
        const float e0 = __shfl_sync(0xffffffffu, s, base + 0);
        const float e1 = __shfl_sync(0xffffffffu, s, base + 1);
        const float e2 = __shfl_sync(0xffffffffu, s, base + 2);
        const float e3 = __shfl_sync(0xffffffffu, s, base + 3);
        const float e4 = __shfl_sync(0xffffffffu, s, base + 4);
        const float e5 = __shfl_sync(0xffffffffu, s, base + 5);
        const float e6 = __shfl_sync(0xffffffffu, s, base + 6);
        const float e7 = __shfl_sync(0xffffffffu, s, base + 7);

        const int i = lane & 7;
        const int g = (i == 0) ? 0 : (i < 4) ? 1 : (i < 7) ? 2 : 3;

        float nr;
        if      (g == 0) nr = fabsf(e0);
        else if (g == 1) nr = sqrtf(e1 * e1 + e2 * e2 + e3 * e3);
        else if (g == 2) nr = sqrtf(e4 * e4 + e5 * e5 + e6 * e6);
        else             nr = fabsf(e7);

        const float sa = 1.f / (1.f + expf(-a[n * 4 + g]));
        const float den = sa * (nr - 1.f) + 1.f + 1e-6f;

        const int which = lane >> 4, b = (lane >> 3) & 1;
        g_qk[which][b][n][i] = s / den;
    }
}

// ---------------------------------------------------------------------------
// Kernel 2: out[b,s,t,:] = q[b,s,:] (geometric product) k[b,t,:]
// STILE=2 + launch_bounds(256, 6): <=42 regs -> 6 blocks/SM = 48 warps,
// more concurrent store streams per SM.
// ---------------------------------------------------------------------------
__global__ __launch_bounds__(256, 6) void gp_kernel(float* __restrict__ out)
{
    const int s0  = blockIdx.x * STILE;
    const int b   = blockIdx.y;
    const int tid = threadIdx.x;

    float q[STILE][8];
#pragma unroll
    for (int si = 0; si < STILE; si++) {
        const float4 qa = *reinterpret_cast<const float4*>(&g_qk[0][b][s0 + si][0]);
        const float4 qb = *reinterpret_cast<const float4*>(&g_qk[0][b][s0 + si][4]);
        q[si][0] = qa.x; q[si][1] = qa.y; q[si][2] = qa.z; q[si][3] = qa.w;
        q[si][4] = qb.x; q[si][5] = qb.y; q[si][6] = qb.z; q[si][7] = qb.w;
    }

    const float* K = &g_qk[1][b][0][0];
    float* obase = out + (((size_t)b * S + s0) * S) * 8;

#pragma unroll
    for (int it = 0; it < 8; it++) {
        const int t = tid + it * 256;
        float4 ka, kb;
        ldg256(K + (size_t)t * 8, ka, kb);
        const float k0 = ka.x, k1 = ka.y, k2 = ka.z, k3 = ka.w;
        const float k4 = kb.x, k5 = kb.y, k6 = kb.z, k7 = kb.w;

#pragma unroll
        for (int si = 0; si < STILE; si++) {
            const float q0 = q[si][0], q1 = q[si][1], q2 = q[si][2], q3 = q[si][3];
            const float q4 = q[si][4], q5 = q[si][5], q6 = q[si][6], q7 = q[si][7];

            float4 o_lo, o_hi;
            o_lo.x = q0*k0 + q1*k1 + q2*k2 + q3*k3 - q4*k4 - q5*k5 - q6*k6 - q7*k7;
            o_lo.y = q0*k1 + q1*k0 - q2*k4 + q4*k2 - q3*k5 + q5*k3 - q6*k7 - q7*k6;
            o_lo.z = q0*k2 + q2*k0 + q1*k4 - q4*k1 - q3*k6 + q6*k3 + q5*k7 + q7*k5;
            o_lo.w = q0*k3 + q3*k0 + q1*k5 - q5*k1 + q2*k6 - q6*k2 - q4*k7 - q7*k4;
            o_hi.x = q0*k4 + q4*k0 + q1*k2 - q2*k1 + q3*k7 + q7*k3 - q5*k6 + q6*k5;
            o_hi.y = q0*k5 + q5*k0 + q1*k3 - q3*k1 - q2*k7 - q7*k2 + q4*k6 - q6*k4;
            o_hi.z = q0*k6 + q6*k0 + q2*k3 - q3*k2 + q1*k7 + q7*k1 - q4*k5 + q5*k4;
            o_hi.w = q0*k7 + q7*k0 + q1*k6 + q6*k1 - q2*k5 - q5*k2 + q3*k4 + q4*k3;

            stg256_cs(obase + (size_t)si * S * 8 + t * 8, o_lo, o_hi);
        }
    }
}

extern "C" void kernel_launch(void* const* d_in, const int* in_sizes, int n_in,
                              void* d_out, int out_size)
{
    const float* x  = (const float*)d_in[0];   // (2, 2048, 8)
    const float* Wq = (const float*)d_in[1];   // (2048, 2048, 4)
    const float* Wk = (const float*)d_in[2];   // (2048, 2048, 4)
    const float* a  = (const float*)d_in[3];   // (3000, 4)
    float* out = (float*)d_out;                // (2, 2048, 2048, 8)

    qk_main<<<QK_BLOCKS, QK_THREADS>>>(x, Wq, Wk, a);
    gp_kernel<<<dim3(S / STILE, B), 256>>>(out);
}